// round 16
// baseline (speedup 1.0000x reference)
#include <cuda_runtime.h>

#define BB 16
#define TT 1024
#define SS 20
#define EE 400
#define HDD 256
#define G4 1024   // 4*HD

// ------------------------- scratch (device globals; no allocs) -------------
__device__ float g_xg_f[BB*TT*G4];     // 64 MB  forward  gate preacts (x @ w_ih_f.T + biases)
__device__ float g_xg_b[BB*TT*G4];     // 64 MB  backward gate preacts (natural t order)
__device__ float g_hf [BB*TT*HDD];     // 16 MB  forward hidden states, scan order
__device__ float g_hb [BB*TT*HDD];     // 16 MB  backward hidden states, scan order
__device__ float g_cat[BB*TT*1024];    // 64 MB  [cm(512) | x2h(512)]
__device__ float g_x2ctx[BB*TT*EE];    // 25.6 MB  mean over S of x2
__device__ int   g_cnt[2*TT];          // per-direction per-step release counters

// ------------------------- mean over S -------------------------------------
__global__ void mean_s_kernel(const float* __restrict__ x2, float* __restrict__ out) {
    int bt  = blockIdx.x;            // 0..B*T-1
    int tid = threadIdx.x;           // 128 threads, 100 active (float4 over E=400)
    if (tid >= EE/4) return;
    const float4* p = (const float4*)(x2 + (size_t)bt * SS * EE);
    float4 acc = make_float4(0.f,0.f,0.f,0.f);
    #pragma unroll
    for (int s = 0; s < SS; s++) {
        float4 v = p[s*(EE/4) + tid];
        acc.x += v.x; acc.y += v.y; acc.z += v.z; acc.w += v.w;
    }
    const float inv = 1.0f / (float)SS;
    acc.x *= inv; acc.y *= inv; acc.z *= inv; acc.w *= inv;
    ((float4*)(out + (size_t)bt*EE))[tid] = acc;
}

// ------------------------- SGEMM: C = A @ W^T + b1 (+b2), optional row mask -
// A: (M,K) row-major, lda; W: (N,K) row-major; C: (M,ldc).
// BM=BN=128, BK=16, 256 threads, 8x8 per thread (4+4 split tiles).
__global__ void sgemm_kernel(const float* __restrict__ A, int lda,
                             const float* __restrict__ W,
                             const float* __restrict__ b1, const float* __restrict__ b2,
                             float* __restrict__ C, int ldc,
                             int M, int N, int K,
                             const int* __restrict__ seq_lens)
{
    __shared__ float As[16][128];
    __shared__ float Ws[16][128];
    const int m0  = blockIdx.x * 128;
    const int n0  = blockIdx.y * 128;
    const int tid = threadIdx.x;
    const int tx  = tid & 15;
    const int ty  = tid >> 4;

    float acc[8][8];
    #pragma unroll
    for (int i = 0; i < 8; i++)
        #pragma unroll
        for (int j = 0; j < 8; j++) acc[i][j] = 0.f;

    for (int k0 = 0; k0 < K; k0 += 16) {
        #pragma unroll
        for (int r = 0; r < 2; r++) {
            int fid = tid*2 + r;
            int row = fid >> 2, kq = fid & 3;
            float4 v = *(const float4*)(A + (size_t)(m0+row)*lda + k0 + kq*4);
            As[kq*4+0][row] = v.x; As[kq*4+1][row] = v.y;
            As[kq*4+2][row] = v.z; As[kq*4+3][row] = v.w;
        }
        #pragma unroll
        for (int r = 0; r < 2; r++) {
            int fid = tid*2 + r;
            int row = fid >> 2, kq = fid & 3;
            float4 v = make_float4(0.f,0.f,0.f,0.f);
            if (n0 + row < N)
                v = *(const float4*)(W + (size_t)(n0+row)*K + k0 + kq*4);
            Ws[kq*4+0][row] = v.x; Ws[kq*4+1][row] = v.y;
            Ws[kq*4+2][row] = v.z; Ws[kq*4+3][row] = v.w;
        }
        __syncthreads();
        #pragma unroll
        for (int kk = 0; kk < 16; kk++) {
            float a[8], b[8];
            *(float4*)&a[0] = *(const float4*)&As[kk][ty*4];
            *(float4*)&a[4] = *(const float4*)&As[kk][64 + ty*4];
            *(float4*)&b[0] = *(const float4*)&Ws[kk][tx*4];
            *(float4*)&b[4] = *(const float4*)&Ws[kk][64 + tx*4];
            #pragma unroll
            for (int i = 0; i < 8; i++)
                #pragma unroll
                for (int j = 0; j < 8; j++)
                    acc[i][j] = fmaf(a[i], b[j], acc[i][j]);
        }
        __syncthreads();
    }

    #pragma unroll
    for (int i = 0; i < 8; i++) {
        int m = m0 + ((i < 4) ? (ty*4 + i) : (64 + ty*4 + i - 4));
        float scale = 1.f;
        if (seq_lens) {
            int bb = m >> 10, t = m & (TT - 1);
            scale = (t < seq_lens[bb]) ? 1.f : 0.f;
        }
        #pragma unroll
        for (int j = 0; j < 8; j++) {
            int n = n0 + ((j < 4) ? (tx*4 + j) : (64 + tx*4 + j - 4));
            if (n < N) {
                float bias = (b1 ? b1[n] : 0.f) + (b2 ? b2[n] : 0.f);
                C[(size_t)m*ldc + n] = (acc[i][j] + bias) * scale;
            }
        }
    }
}

// ------------------------- persistent bidirectional LSTM recurrence --------
// 128 CTAs: blocks 0..63 forward, 64..127 backward. Each CTA owns 4 hidden
// units (x all 16 batches) and keeps its 16 w_hh rows in registers.
// Per-step h broadcast goes through the per-step rows of g_hf/g_hb (fresh
// addresses -> no L1 staleness) with fence + counter release/acquire.
__device__ __forceinline__ float sigm(float x) { return 1.f / (1.f + __expf(-x)); }

__global__ void lstm_kernel(const int* __restrict__ seq_lens,
                            const float* __restrict__ w_hh_f,
                            const float* __restrict__ w_hh_b)
{
    const int dir   = blockIdx.x >> 6;      // 0 fwd, 1 bwd
    const int slice = blockIdx.x & 63;      // 64 slices x 4 units
    const int u0    = slice * 4;
    const float* whh = dir ? w_hh_b : w_hh_f;
    const float* xg  = dir ? g_xg_b : g_xg_f;
    float*       hs  = dir ? g_hb   : g_hf;
    int*          cnt_rw = &g_cnt[dir * TT];
    volatile int* cnt_ro = (volatile int*)cnt_rw;

    __shared__ float Hs[16 * 264];   // h_{t-1}: 16 batches x 256 (padded stride 264)
    __shared__ float Gs[16 * 17];    // gate partial sums: 16 batches x 16 rows (pad 17)
    __shared__ int   slen[16];

    const int tid  = threadIdx.x;         // 256
    const int bh   = tid >> 6;            // batch group 0..3 (4 batches each)
    const int cell = tid & 63;
    const int rp   = cell >> 3;           // row pair 0..7
    const int kc   = cell & 7;            // k chunk 0..7

    // local row index lr in 0..15 maps to gate=(lr>>2), unit=u0+(lr&3)
    const int lr0 = rp*2, lr1 = rp*2 + 1;
    const int grow0 = (lr0 >> 2)*256 + u0 + (lr0 & 3);
    const int grow1 = (lr1 >> 2)*256 + u0 + (lr1 & 3);

    // pin this thread's w_hh slice in registers: rows lr0,lr1; k = kc*4 + 32j + i
    float4 w0[8], w1[8];
    #pragma unroll
    for (int j = 0; j < 8; j++) {
        w0[j] = *(const float4*)(whh + (size_t)grow0*256 + kc*4 + j*32);
        w1[j] = *(const float4*)(whh + (size_t)grow1*256 + kc*4 + j*32);
    }

    if (tid < 16) slen[tid] = seq_lens[tid];
    for (int i = tid; i < 16*264; i += 256) Hs[i] = 0.f;
    __syncthreads();

    float c_state = 0.f;    // phase-2 cell state (tid < 64)

    for (int t = 0; t < TT; t++) {
        // ---- phase-2 xg prefetch (independent of h; issue early) ----
        float xgi = 0.f, xgf = 0.f, xgg = 0.f, xgo = 0.f;
        if (tid < 64) {
            int b = tid >> 2, u = tid & 3;
            int trow = t;
            if (dir) { int L = slen[b]; trow = (t < L) ? (L - 1 - t) : t; }
            const float* xp = xg + ((size_t)(b*TT + trow))*1024 + u0 + u;
            xgi = xp[0]; xgf = xp[256]; xgg = xp[512]; xgo = xp[768];
        }

        if (t > 0) {
            if (tid == 0) {
                while (cnt_ro[t-1] < 64) { }
                __threadfence();   // acquire
            }
            __syncthreads();
            // load h_{t-1} (16x256 f32) into Hs
            {
                int b = tid >> 4, l = tid & 15;
                const float4* src = (const float4*)(hs + ((size_t)(b*TT + (t-1)))*256);
                float4* dst = (float4*)&Hs[b*264];
                #pragma unroll
                for (int j = 0; j < 4; j++)
                    dst[l + 16*j] = src[l + 16*j];
            }
            __syncthreads();
        }

        // ---- phase 1: gate dot products ----
        #pragma unroll
        for (int bi = 0; bi < 4; bi++) {
            int b = bh*4 + bi;
            const float4* hrow = (const float4*)&Hs[b*264];
            float p0 = 0.f, p1 = 0.f;
            #pragma unroll
            for (int j = 0; j < 8; j++) {
                float4 h4 = hrow[kc + 8*j];
                p0 = fmaf(w0[j].x, h4.x, p0); p0 = fmaf(w0[j].y, h4.y, p0);
                p0 = fmaf(w0[j].z, h4.z, p0); p0 = fmaf(w0[j].w, h4.w, p0);
                p1 = fmaf(w1[j].x, h4.x, p1); p1 = fmaf(w1[j].y, h4.y, p1);
                p1 = fmaf(w1[j].z, h4.z, p1); p1 = fmaf(w1[j].w, h4.w, p1);
            }
            #pragma unroll
            for (int off = 4; off; off >>= 1) {
                p0 += __shfl_down_sync(0xffffffffu, p0, off);
                p1 += __shfl_down_sync(0xffffffffu, p1, off);
            }
            if (kc == 0) {
                Gs[b*17 + lr0] = p0;
                Gs[b*17 + lr1] = p1;
            }
        }
        __syncthreads();

        // ---- phase 2: nonlinearity + state update (64 threads) ----
        if (tid < 64) {
            int b = tid >> 2, u = tid & 3;
            float gi = Gs[b*17 +  0 + u] + xgi;
            float gf = Gs[b*17 +  4 + u] + xgf;
            float gg = Gs[b*17 +  8 + u] + xgg;
            float go = Gs[b*17 + 12 + u] + xgo;
            float i_ = sigm(gi), f_ = sigm(gf), g_ = tanhf(gg), o_ = sigm(go);
            c_state = f_ * c_state + i_ * g_;
            float hval = o_ * tanhf(c_state);
            hs[((size_t)(b*TT + t))*256 + u0 + u] = hval;
        }
        __threadfence();     // release: stores visible before counter bump
        __syncthreads();
        if (tid == 0) atomicAdd(&cnt_rw[t], 1);
    }
}

// ------------------------- masked cumulative mean + backward reorder -------
__global__ void cumsum_kernel(const int* __restrict__ seq_lens) {
    int b = blockIdx.x;
    int u = threadIdx.x;      // 512
    int L = seq_lens[b];
    const float* hf = g_hf + (size_t)b*TT*256;
    const float* hb = g_hb + (size_t)b*TT*256;
    float* out = g_cat + (size_t)b*TT*1024;
    float sum = 0.f;
    for (int t = 0; t < TT; t++) {
        float v;
        if (u < 256) {
            v = hf[(size_t)t*256 + u];
        } else {
            int r = (t < L) ? (L - 1 - t) : t;    // ridx involution gather
            v = hb[(size_t)r*256 + (u - 256)];
        }
        if (t < L) sum += v;
        out[(size_t)t*1024 + u] = sum / (float)(t + 1);
    }
}

// ------------------------- launch ------------------------------------------
extern "C" void kernel_launch(void* const* d_in, const int* in_sizes, int n_in,
                              void* d_out, int out_size) {
    const float* x1        = (const float*)d_in[0];
    const float* x2        = (const float*)d_in[1];
    const int*   seq_lens  = (const int*)  d_in[2];
    // d_in[3] mha_w, d_in[4] mha_b: provably unused (softmax collapse)
    const float* mlp_mha_w = (const float*)d_in[5];
    const float* mlp_mha_b = (const float*)d_in[6];
    const float* w_ih_f    = (const float*)d_in[7];
    const float* w_hh_f    = (const float*)d_in[8];
    const float* b_ih_f    = (const float*)d_in[9];
    const float* b_hh_f    = (const float*)d_in[10];
    const float* w_ih_b    = (const float*)d_in[11];
    const float* w_hh_b    = (const float*)d_in[12];
    const float* b_ih_b    = (const float*)d_in[13];
    const float* b_hh_b    = (const float*)d_in[14];
    const float* mlp_w     = (const float*)d_in[15];
    const float* mlp_b     = (const float*)d_in[16];
    float* out = (float*)d_out;

    void *p_cnt, *p_x2ctx, *p_cat, *p_xgf, *p_xgb;
    cudaGetSymbolAddress(&p_cnt,   g_cnt);
    cudaGetSymbolAddress(&p_x2ctx, g_x2ctx);
    cudaGetSymbolAddress(&p_cat,   g_cat);
    cudaGetSymbolAddress(&p_xgf,   g_xg_f);
    cudaGetSymbolAddress(&p_xgb,   g_xg_b);

    const int M = BB*TT;   // 16384

    // reset recurrence counters (every replay)
    cudaMemsetAsync(p_cnt, 0, 2*TT*sizeof(int));

    // x2 mean over S
    mean_s_kernel<<<BB*TT, 128>>>(x2, (float*)p_x2ctx);

    // x2h = x2ctx @ mlp_mha_w.T + b  -> cat[:, 512:1024]
    sgemm_kernel<<<dim3(M/128, 512/128), 256>>>(
        (const float*)p_x2ctx, EE, mlp_mha_w, mlp_mha_b, nullptr,
        (float*)p_cat + 512, 1024, M, 512, EE, nullptr);

    // gate preactivations (forward & backward; backward in natural t order)
    sgemm_kernel<<<dim3(M/128, 1024/128), 256>>>(
        x1, EE, w_ih_f, b_ih_f, b_hh_f, (float*)p_xgf, 1024, M, 1024, EE, nullptr);
    sgemm_kernel<<<dim3(M/128, 1024/128), 256>>>(
        x1, EE, w_ih_b, b_ih_b, b_hh_b, (float*)p_xgb, 1024, M, 1024, EE, nullptr);

    // persistent bidirectional recurrence
    lstm_kernel<<<128, 256>>>(seq_lens, w_hh_f, w_hh_b);

    // masked cumulative mean (+ backward reorder) -> cat[:, 0:512]
    cumsum_kernel<<<BB, 512>>>(seq_lens);

    // out = cat @ mlp_w.T + mlp_b, masked rows zeroed
    sgemm_kernel<<<dim3(M/128, (EE + 127)/128), 256>>>(
        (const float*)p_cat, 1024, mlp_w, mlp_b, nullptr,
        out, EE, M, EE, 1024, seq_lens);
}

// round 17
// speedup vs baseline: 1.2284x; 1.2284x over previous
#include <cuda_runtime.h>

#define BB 16
#define TT 1024
#define SS 20
#define EE 400
#define HDD 256
#define G4 1024   // 4*HD

typedef unsigned long long u64;

__device__ __forceinline__ u64 ffma2(u64 a, u64 b, u64 c) {
    u64 d; asm("fma.rn.f32x2 %0, %1, %2, %3;" : "=l"(d) : "l"(a), "l"(b), "l"(c)); return d;
}
__device__ __forceinline__ u64 pack2(float x, float y) {
    u64 d; asm("mov.b64 %0, {%1, %2};" : "=l"(d) : "f"(x), "f"(y)); return d;
}
__device__ __forceinline__ float2 unpack2(u64 v) {
    float2 r; asm("mov.b64 {%0, %1}, %2;" : "=f"(r.x), "=f"(r.y) : "l"(v)); return r;
}

// ------------------------- scratch (device globals; no allocs) -------------
__device__ float g_xg_f[BB*TT*G4];     // forward  gate preacts
__device__ float g_xg_b[BB*TT*G4];     // backward gate preacts (natural t order)
__device__ float g_hf [BB*TT*HDD];     // forward hidden states, scan order
__device__ float g_hb [BB*TT*HDD];     // backward hidden states, scan order
__device__ float g_cat[BB*TT*1024];    // [cm(512) | x2h(512)]
__device__ float g_x2ctx[BB*TT*EE];    // mean over S of x2
__device__ int   g_cnt[2*TT];          // per-direction per-step release counters

// ------------------------- mean over S -------------------------------------
__global__ void mean_s_kernel(const float* __restrict__ x2, float* __restrict__ out) {
    int bt  = blockIdx.x;
    int tid = threadIdx.x;
    if (tid >= EE/4) return;
    const float4* p = (const float4*)(x2 + (size_t)bt * SS * EE);
    float4 acc = make_float4(0.f,0.f,0.f,0.f);
    #pragma unroll
    for (int s = 0; s < SS; s++) {
        float4 v = p[s*(EE/4) + tid];
        acc.x += v.x; acc.y += v.y; acc.z += v.z; acc.w += v.w;
    }
    const float inv = 1.0f / (float)SS;
    acc.x *= inv; acc.y *= inv; acc.z *= inv; acc.w *= inv;
    ((float4*)(out + (size_t)bt*EE))[tid] = acc;
}

// ------------------------- SGEMM: C = A @ W^T + b1 (+b2), optional row mask -
// BM=BN=128, BK=16, 256 threads, 8x8 per thread, FFMA2 inner loop.
__global__ __launch_bounds__(256) void sgemm_kernel(
        const float* __restrict__ A, int lda,
        const float* __restrict__ W,
        const float* __restrict__ b1, const float* __restrict__ b2,
        float* __restrict__ C, int ldc,
        int M, int N, int K,
        const int* __restrict__ seq_lens)
{
    __shared__ float As[16][128];
    __shared__ float Ws[16][128];
    const int m0  = blockIdx.x * 128;
    const int n0  = blockIdx.y * 128;
    const int tid = threadIdx.x;
    const int tx  = tid & 15;
    const int ty  = tid >> 4;

    u64 acc2[4][8];                     // i-pairs x j, packed f32x2
    #pragma unroll
    for (int i = 0; i < 4; i++)
        #pragma unroll
        for (int j = 0; j < 8; j++) acc2[i][j] = 0ull;

    for (int k0 = 0; k0 < K; k0 += 16) {
        #pragma unroll
        for (int r = 0; r < 2; r++) {
            int fid = tid*2 + r;
            int row = fid >> 2, kq = fid & 3;
            float4 v = *(const float4*)(A + (size_t)(m0+row)*lda + k0 + kq*4);
            As[kq*4+0][row] = v.x; As[kq*4+1][row] = v.y;
            As[kq*4+2][row] = v.z; As[kq*4+3][row] = v.w;
        }
        #pragma unroll
        for (int r = 0; r < 2; r++) {
            int fid = tid*2 + r;
            int row = fid >> 2, kq = fid & 3;
            float4 v = make_float4(0.f,0.f,0.f,0.f);
            if (n0 + row < N)
                v = *(const float4*)(W + (size_t)(n0+row)*K + k0 + kq*4);
            Ws[kq*4+0][row] = v.x; Ws[kq*4+1][row] = v.y;
            Ws[kq*4+2][row] = v.z; Ws[kq*4+3][row] = v.w;
        }
        __syncthreads();
        #pragma unroll
        for (int kk = 0; kk < 16; kk++) {
            ulonglong2 aA = *(const ulonglong2*)&As[kk][ty*4];
            ulonglong2 aB = *(const ulonglong2*)&As[kk][64 + ty*4];
            u64 ap[4] = {aA.x, aA.y, aB.x, aB.y};
            float bb[8];
            *(float4*)&bb[0] = *(const float4*)&Ws[kk][tx*4];
            *(float4*)&bb[4] = *(const float4*)&Ws[kk][64 + tx*4];
            #pragma unroll
            for (int j = 0; j < 8; j++) {
                u64 bj = pack2(bb[j], bb[j]);
                #pragma unroll
                for (int i2 = 0; i2 < 4; i2++)
                    acc2[i2][j] = ffma2(ap[i2], bj, acc2[i2][j]);
            }
        }
        __syncthreads();
    }

    #pragma unroll
    for (int i2 = 0; i2 < 4; i2++) {
        int i0 = 2*i2, i1 = 2*i2 + 1;
        int m_a = m0 + ((i0 < 4) ? (ty*4 + i0) : (64 + ty*4 + i0 - 4));
        int m_b = m0 + ((i1 < 4) ? (ty*4 + i1) : (64 + ty*4 + i1 - 4));
        float sc_a = 1.f, sc_b = 1.f;
        if (seq_lens) {
            sc_a = ((m_a & (TT-1)) < seq_lens[m_a >> 10]) ? 1.f : 0.f;
            sc_b = ((m_b & (TT-1)) < seq_lens[m_b >> 10]) ? 1.f : 0.f;
        }
        #pragma unroll
        for (int j = 0; j < 8; j++) {
            int n = n0 + ((j < 4) ? (tx*4 + j) : (64 + tx*4 + j - 4));
            if (n < N) {
                float bias = (b1 ? b1[n] : 0.f) + (b2 ? b2[n] : 0.f);
                float2 v = unpack2(acc2[i2][j]);
                C[(size_t)m_a*ldc + n] = (v.x + bias) * sc_a;
                C[(size_t)m_b*ldc + n] = (v.y + bias) * sc_b;
            }
        }
    }
}

// ------------------------- persistent bidirectional LSTM recurrence --------
// 128 CTAs: 0..63 forward, 64..127 backward. Each CTA owns 4 hidden units
// x 16 batches, w_hh rows pinned in registers (packed f32x2).
// Release: each of the 64 writer threads does st.global then red.release on
// the per-step counter (target 64 CTA x 64 writers = 4096).
// Acquire: tid0 polls ld.acquire.gpu, then __syncthreads extends ordering.
__device__ __forceinline__ float sigm(float x) { return 1.f / (1.f + __expf(-x)); }

__global__ __launch_bounds__(256) void lstm_kernel(
        const int* __restrict__ seq_lens,
        const float* __restrict__ w_hh_f,
        const float* __restrict__ w_hh_b)
{
    const int dir   = blockIdx.x >> 6;
    const int slice = blockIdx.x & 63;
    const int u0    = slice * 4;
    const float* whh = dir ? w_hh_b : w_hh_f;
    const float* xg  = dir ? g_xg_b : g_xg_f;
    float*       hs  = dir ? g_hb   : g_hf;
    int*         cnt = &g_cnt[dir * TT];

    __shared__ float Hs[16 * 264];   // h_{t-1}: 16 batches x 256 (pad 264)
    __shared__ float Gs[16 * 17];    // gate partials: 16 batches x 16 rows
    __shared__ int   slen[16];

    const int tid  = threadIdx.x;    // 256
    const int bh   = tid >> 6;       // batch group 0..3
    const int cell = tid & 63;
    const int rp   = cell >> 3;      // row pair 0..7
    const int kc   = cell & 7;       // k chunk 0..7

    const int lr0 = rp*2, lr1 = rp*2 + 1;
    const int grow0 = (lr0 >> 2)*256 + u0 + (lr0 & 3);
    const int grow1 = (lr1 >> 2)*256 + u0 + (lr1 & 3);

    // pinned w_hh slice, pre-paired for f32x2
    ulonglong2 w0p[8], w1p[8];
    #pragma unroll
    for (int j = 0; j < 8; j++) {
        w0p[j] = *(const ulonglong2*)(whh + (size_t)grow0*256 + kc*4 + j*32);
        w1p[j] = *(const ulonglong2*)(whh + (size_t)grow1*256 + kc*4 + j*32);
    }

    if (tid < 16) slen[tid] = seq_lens[tid];
    for (int i = tid; i < 16*264; i += 256) Hs[i] = 0.f;
    __syncthreads();

    float c_state = 0.f;

    for (int t = 0; t < TT; t++) {
        // xg prefetch (independent of h; overlap with the wait)
        float xgi = 0.f, xgf = 0.f, xgg = 0.f, xgo = 0.f;
        if (tid < 64) {
            int b = tid >> 2, u = tid & 3;
            int trow = t;
            if (dir) { int L = slen[b]; trow = (t < L) ? (L - 1 - t) : t; }
            const float* xp = xg + ((size_t)(b*TT + trow))*1024 + u0 + u;
            xgi = xp[0]; xgf = xp[256]; xgg = xp[512]; xgo = xp[768];
        }

        if (t > 0) {
            if (tid == 0) {
                int v;
                do {
                    asm volatile("ld.acquire.gpu.global.s32 %0, [%1];"
                                 : "=r"(v) : "l"(cnt + t - 1) : "memory");
                } while (v < 4096);
            }
            __syncthreads();
            {   // load h_{t-1} (16x256 f32) into Hs
                int b = tid >> 4, l = tid & 15;
                const float4* src = (const float4*)(hs + ((size_t)(b*TT + (t-1)))*256);
                float4* dst = (float4*)&Hs[b*264];
                #pragma unroll
                for (int j = 0; j < 4; j++)
                    dst[l + 16*j] = src[l + 16*j];
            }
            __syncthreads();
        }

        // phase 1: gate dot products (FFMA2)
        #pragma unroll
        for (int bi = 0; bi < 4; bi++) {
            int b = bh*4 + bi;
            const ulonglong2* hrow2 = (const ulonglong2*)&Hs[b*264];
            u64 p0v = 0ull, p1v = 0ull;
            #pragma unroll
            for (int j = 0; j < 8; j++) {
                ulonglong2 h2 = hrow2[kc + 8*j];
                p0v = ffma2(w0p[j].x, h2.x, p0v);
                p0v = ffma2(w0p[j].y, h2.y, p0v);
                p1v = ffma2(w1p[j].x, h2.x, p1v);
                p1v = ffma2(w1p[j].y, h2.y, p1v);
            }
            float2 f0 = unpack2(p0v); float p0 = f0.x + f0.y;
            float2 f1 = unpack2(p1v); float p1 = f1.x + f1.y;
            #pragma unroll
            for (int off = 4; off; off >>= 1) {
                p0 += __shfl_down_sync(0xffffffffu, p0, off);
                p1 += __shfl_down_sync(0xffffffffu, p1, off);
            }
            if (kc == 0) {
                Gs[b*17 + lr0] = p0;
                Gs[b*17 + lr1] = p1;
            }
        }
        __syncthreads();

        // phase 2: nonlinearity + state update + release (64 threads)
        if (tid < 64) {
            int b = tid >> 2, u = tid & 3;
            float gi = Gs[b*17 +  0 + u] + xgi;
            float gf = Gs[b*17 +  4 + u] + xgf;
            float gg = Gs[b*17 +  8 + u] + xgg;
            float go = Gs[b*17 + 12 + u] + xgo;
            float i_ = sigm(gi), f_ = sigm(gf), g_ = tanhf(gg), o_ = sigm(go);
            c_state = f_ * c_state + i_ * g_;
            float hval = o_ * tanhf(c_state);
            hs[((size_t)(b*TT + t))*256 + u0 + u] = hval;
            asm volatile("red.release.gpu.global.add.s32 [%0], %1;"
                         :: "l"(cnt + t), "r"(1) : "memory");
        }
        // no trailing barrier: next step's post-poll barriers protect Hs/Gs reuse
    }
}

// ------------------------- masked cumulative mean + backward reorder -------
// grid = B*4 CTAs of 128 threads; unroll t by 8 for MLP.
__global__ void cumsum_kernel(const int* __restrict__ seq_lens) {
    int b = blockIdx.x >> 2;
    int u = (blockIdx.x & 3) * 128 + threadIdx.x;   // 0..511
    int L = seq_lens[b];
    const float* hf = g_hf + (size_t)b*TT*256;
    const float* hb = g_hb + (size_t)b*TT*256;
    float* out = g_cat + (size_t)b*TT*1024;
    float sum = 0.f;
    for (int t0 = 0; t0 < TT; t0 += 8) {
        float v[8];
        #pragma unroll
        for (int k = 0; k < 8; k++) {
            int t = t0 + k;
            if (u < 256) {
                v[k] = hf[(size_t)t*256 + u];
            } else {
                int r = (t < L) ? (L - 1 - t) : t;
                v[k] = hb[(size_t)r*256 + (u - 256)];
            }
        }
        #pragma unroll
        for (int k = 0; k < 8; k++) {
            int t = t0 + k;
            if (t < L) sum += v[k];
            out[(size_t)t*1024 + u] = __fdividef(sum, (float)(t + 1));
        }
    }
}

// ------------------------- launch ------------------------------------------
extern "C" void kernel_launch(void* const* d_in, const int* in_sizes, int n_in,
                              void* d_out, int out_size) {
    const float* x1        = (const float*)d_in[0];
    const float* x2        = (const float*)d_in[1];
    const int*   seq_lens  = (const int*)  d_in[2];
    // d_in[3] mha_w, d_in[4] mha_b: provably unused (softmax collapse)
    const float* mlp_mha_w = (const float*)d_in[5];
    const float* mlp_mha_b = (const float*)d_in[6];
    const float* w_ih_f    = (const float*)d_in[7];
    const float* w_hh_f    = (const float*)d_in[8];
    const float* b_ih_f    = (const float*)d_in[9];
    const float* b_hh_f    = (const float*)d_in[10];
    const float* w_ih_b    = (const float*)d_in[11];
    const float* w_hh_b    = (const float*)d_in[12];
    const float* b_ih_b    = (const float*)d_in[13];
    const float* b_hh_b    = (const float*)d_in[14];
    const float* mlp_w     = (const float*)d_in[15];
    const float* mlp_b     = (const float*)d_in[16];
    float* out = (float*)d_out;

    void *p_cnt, *p_x2ctx, *p_cat, *p_xgf, *p_xgb;
    cudaGetSymbolAddress(&p_cnt,   g_cnt);
    cudaGetSymbolAddress(&p_x2ctx, g_x2ctx);
    cudaGetSymbolAddress(&p_cat,   g_cat);
    cudaGetSymbolAddress(&p_xgf,   g_xg_f);
    cudaGetSymbolAddress(&p_xgb,   g_xg_b);

    const int M = BB*TT;   // 16384

    cudaMemsetAsync(p_cnt, 0, 2*TT*sizeof(int));

    mean_s_kernel<<<BB*TT, 128>>>(x2, (float*)p_x2ctx);

    // x2h = x2ctx @ mlp_mha_w.T + b  -> cat[:, 512:1024]
    sgemm_kernel<<<dim3(M/128, 512/128), 256>>>(
        (const float*)p_x2ctx, EE, mlp_mha_w, mlp_mha_b, nullptr,
        (float*)p_cat + 512, 1024, M, 512, EE, nullptr);

    // gate preactivations
    sgemm_kernel<<<dim3(M/128, 1024/128), 256>>>(
        x1, EE, w_ih_f, b_ih_f, b_hh_f, (float*)p_xgf, 1024, M, 1024, EE, nullptr);
    sgemm_kernel<<<dim3(M/128, 1024/128), 256>>>(
        x1, EE, w_ih_b, b_ih_b, b_hh_b, (float*)p_xgb, 1024, M, 1024, EE, nullptr);

    // persistent bidirectional recurrence
    lstm_kernel<<<128, 256>>>(seq_lens, w_hh_f, w_hh_b);

    // masked cumulative mean (+ backward reorder) -> cat[:, 0:512]
    cumsum_kernel<<<BB*4, 128>>>(seq_lens);

    // out = cat @ mlp_w.T + mlp_b, masked rows zeroed
    sgemm_kernel<<<dim3(M/128, (EE + 127)/128), 256>>>(
        (const float*)p_cat, 1024, mlp_w, mlp_b, nullptr,
        out, EE, M, EE, 1024, seq_lens);
}